// round 3
// baseline (speedup 1.0000x reference)
#include <cuda_runtime.h>
#include <cuda_bf16.h>
#include <math.h>
#include <cstddef>

#define T_DIM 512
#define B_DIM 128
#define D_DIM 256
#define H_DIM 512

typedef unsigned long long u64;

// Scratch for precomputed input projection (+ biases). __device__ global =
// the sanctioned allocation-free scratch mechanism.
__device__ float g_xin[(size_t)T_DIM * B_DIM * H_DIM];

__device__ __forceinline__ void fma2(u64 &acc, u64 a, u64 b) {
    asm("fma.rn.f32x2 %0, %1, %2, %0;" : "+l"(acc) : "l"(a), "l"(b));
}
__device__ __forceinline__ float f2sum(u64 v) {
    float2 f;
    f = *reinterpret_cast<float2 *>(&v);
    return f.x + f.y;
}

// ---------------------------------------------------------------------------
// Kernel 1: xin[t,b,n] = x[t,b,:] . W_in[n,:] + b_in[n] + b_lat[n]
// GEMM: M = T*B = 65536 (rows of x), N = 512, K = 256. Both operands K-major.
// Block tile 128x128, BK=16, 256 threads, 8x8 per-thread tile, f32x2 FMAs.
// ---------------------------------------------------------------------------
__global__ void __launch_bounds__(256, 1)
xin_gemm(const float *__restrict__ x, const float *__restrict__ W_in,
         const float *__restrict__ b_in, const float *__restrict__ b_lat) {
    __shared__ float As[128 * 16];   // [m][k], stride 16 floats
    __shared__ float Bs[128 * 18];   // [n][k], stride 18 floats (pad: odd # of 8B units)

    const int tid = threadIdx.x;
    const int tx = tid & 15;         // n-owner (interleaved: n = n0 + tx + 16*j)
    const int ty = tid >> 4;         // m-owner (contiguous: m = m0 + ty*8 + i)
    const int m0 = blockIdx.y * 128;
    const int n0 = blockIdx.x * 128;

    u64 acc[8][8];
#pragma unroll
    for (int i = 0; i < 8; i++)
#pragma unroll
        for (int j = 0; j < 8; j++) acc[i][j] = 0ull;

    for (int kc = 0; kc < D_DIM; kc += 16) {
        __syncthreads();
        // Load A tile: 128 rows x 16 k (x is row-major with K contiguous)
#pragma unroll
        for (int u = 0; u < 2; u++) {
            int idx = tid + u * 256;
            int row = idx >> 2, c4 = idx & 3;
            float4 v = *reinterpret_cast<const float4 *>(
                &x[(size_t)(m0 + row) * D_DIM + kc + c4 * 4]);
            *reinterpret_cast<float4 *>(&As[row * 16 + c4 * 4]) = v;
        }
        // Load B tile: 128 rows (n) x 16 k from W_in (row-major, K contiguous)
#pragma unroll
        for (int u = 0; u < 4; u++) {
            int idx = tid + u * 256;
            int row = idx >> 3, cp = idx & 7;
            float2 v = *reinterpret_cast<const float2 *>(
                &W_in[(size_t)(n0 + row) * D_DIM + kc + cp * 2]);
            *reinterpret_cast<float2 *>(&Bs[row * 18 + cp * 2]) = v;
        }
        __syncthreads();

        const u64 *As2 = reinterpret_cast<const u64 *>(As);
        const u64 *Bs2 = reinterpret_cast<const u64 *>(Bs);
#pragma unroll
        for (int kp = 0; kp < 8; kp++) {
            u64 a2[8], b2[8];
#pragma unroll
            for (int i = 0; i < 8; i++) a2[i] = As2[(ty * 8 + i) * 8 + kp];  // broadcast
#pragma unroll
            for (int j = 0; j < 8; j++) b2[j] = Bs2[(tx + 16 * j) * 9 + kp]; // stride 9 (odd) -> CF
#pragma unroll
            for (int i = 0; i < 8; i++)
#pragma unroll
                for (int j = 0; j < 8; j++) fma2(acc[i][j], a2[i], b2[j]);
        }
    }

#pragma unroll
    for (int j = 0; j < 8; j++) {
        int n = n0 + tx + 16 * j;
        float bias = __ldg(&b_in[n]) + __ldg(&b_lat[n]);
#pragma unroll
        for (int i = 0; i < 8; i++) {
            g_xin[(size_t)(m0 + ty * 8 + i) * H_DIM + n] = f2sum(acc[i][j]) + bias;
        }
    }
}

// ---------------------------------------------------------------------------
// Kernel 2: the scan. 16 clusters x 8 CTAs. Cluster c owns batches
// [c*8, c*8+8); CTA rank r owns output rows [r*64, r*64+64) and keeps its
// W_lat slice resident in smem. Per step: h (8x512) from out[t-1] (or h0),
// 64x8x512 GEMM, tanh, write out[t]. barrier.cluster is the only sync.
// ---------------------------------------------------------------------------
#define SMEM_SCAN_FLOATS (64 * 512 + 8 * 512 + 512)

__global__ void __cluster_dims__(8, 1, 1) __launch_bounds__(256, 1)
rnn_scan(const float *__restrict__ h0, const float *__restrict__ W_lat,
         float *__restrict__ out) {
    extern __shared__ float smem[];
    float *Wsm = smem;                    // 64 x 512
    float *hsm = smem + 64 * 512;         // 8 x 512
    float *stage = hsm + 8 * 512;         // 8 x 64

    const int tid = threadIdx.x;
    const int r = blockIdx.x & 7;   // cluster rank -> j-slice
    const int g = blockIdx.x >> 3;  // cluster id  -> batch group
    const int j0g = r * 64;
    const int b0 = g * 8;

    // Load W_lat rows [j0g, j0g+64) into smem (once).
    {
        const float4 *src = reinterpret_cast<const float4 *>(W_lat + (size_t)j0g * H_DIM);
        float4 *dst = reinterpret_cast<float4 *>(Wsm);
        for (int i = tid; i < 64 * 128; i += 256) dst[i] = src[i];
    }

    const int lane = tid & 31;
    const int w = tid >> 5;       // warp 0..7 -> rows j = j0g + w*8 .. +8
    const int a = lane >> 4;      // batch half: b = b0 + a*4 .. +4
    const int ks = lane & 15;     // 16-way K split (interleaved k-pairs)

    const u64 *Wp = reinterpret_cast<const u64 *>(Wsm) + (size_t)(w * 8) * 256;
    const u64 *hp = reinterpret_cast<const u64 *>(hsm) + (size_t)(a * 4) * 256;

    for (int t = 0; t < T_DIM; t++) {
        // ---- load h for our 8 batches (contiguous 4096 floats) ----
        const float *hsrc = (t == 0) ? (h0 + (size_t)b0 * H_DIM)
                                     : (out + ((size_t)(t - 1) * B_DIM + b0) * H_DIM);
        const float4 *hs4 = reinterpret_cast<const float4 *>(hsrc);
        float4 *hd4 = reinterpret_cast<float4 *>(hsm);
#pragma unroll
        for (int u = 0; u < 4; u++) hd4[tid + 256 * u] = __ldcg(&hs4[tid + 256 * u]);

        // ---- prefetch xin for this lane's (potential) outputs ----
        float xpre[4] = {0.f, 0.f, 0.f, 0.f};
        if (ks < 8) {
            const float *xp = g_xin + ((size_t)t * B_DIM + b0 + a * 4) * H_DIM + j0g + w * 8 + ks;
#pragma unroll
            for (int bb = 0; bb < 4; bb++) xpre[bb] = __ldcg(xp + (size_t)bb * H_DIM);
        }

        __syncthreads();  // hsm ready

        // ---- GEMM: acc[jj][bb] over this lane's 16 k-pairs (stride-16) ----
        u64 acc[8][4];
#pragma unroll
        for (int jj = 0; jj < 8; jj++)
#pragma unroll
            for (int bb = 0; bb < 4; bb++) acc[jj][bb] = 0ull;

#pragma unroll 4
        for (int i = 0; i < 16; i++) {
            int kp = i * 16 + ks;
            u64 wr[8], hr[4];
#pragma unroll
            for (int jj = 0; jj < 8; jj++) wr[jj] = Wp[(size_t)jj * 256 + kp];
#pragma unroll
            for (int bb = 0; bb < 4; bb++) hr[bb] = hp[(size_t)bb * 256 + kp];
#pragma unroll
            for (int jj = 0; jj < 8; jj++)
#pragma unroll
                for (int bb = 0; bb < 4; bb++) fma2(acc[jj][bb], wr[jj], hr[bb]);
        }

        // ---- reduce: lo+hi, then butterfly over the 16-lane K group ----
        float accf[8][4];
#pragma unroll
        for (int jj = 0; jj < 8; jj++)
#pragma unroll
            for (int bb = 0; bb < 4; bb++) accf[jj][bb] = f2sum(acc[jj][bb]);

#pragma unroll
        for (int off = 8; off >= 1; off >>= 1) {
#pragma unroll
            for (int jj = 0; jj < 8; jj++)
#pragma unroll
                for (int bb = 0; bb < 4; bb++)
                    accf[jj][bb] += __shfl_xor_sync(0xffffffffu, accf[jj][bb], off);
        }

        // ---- epilogue: lane ks<8 writes row jj=ks for its 4 batches ----
        // Branch-free select (dynamic reg index would spill to local mem).
        float sel[4];
#pragma unroll
        for (int bb = 0; bb < 4; bb++) {
            float v = accf[0][bb];
#pragma unroll
            for (int jj = 1; jj < 8; jj++) v = (ks == jj) ? accf[jj][bb] : v;
            sel[bb] = v;
        }
        if (ks < 8) {
#pragma unroll
            for (int bb = 0; bb < 4; bb++) {
                float v = tanhf(sel[bb] + xpre[bb]);
                stage[(a * 4 + bb) * 64 + w * 8 + ks] = v;
            }
        }

        __syncthreads();  // stage ready

        // ---- coalesced write of our 8x64 block of out[t] ----
        float *od = out + ((size_t)t * B_DIM + b0) * H_DIM + j0g;
#pragma unroll
        for (int u = 0; u < 2; u++) {
            int idx = tid + 256 * u;
            int bb = idx >> 6, col = idx & 63;
            __stcg(od + (size_t)bb * H_DIM + col, stage[idx]);
        }

        // ---- cluster barrier: publish out[t] to the 7 peer CTAs ----
        asm volatile("barrier.cluster.arrive.aligned;" ::: "memory");
        asm volatile("barrier.cluster.wait.aligned;" ::: "memory");
    }
}

// ---------------------------------------------------------------------------
extern "C" void kernel_launch(void *const *d_in, const int *in_sizes, int n_in,
                              void *d_out, int out_size) {
    const float *x     = (const float *)d_in[0];
    const float *h     = (const float *)d_in[1];
    const float *W_in  = (const float *)d_in[2];
    const float *b_in  = (const float *)d_in[3];
    const float *W_lat = (const float *)d_in[4];
    const float *b_lat = (const float *)d_in[5];
    float *out = (float *)d_out;

    dim3 gx(H_DIM / 128, (T_DIM * B_DIM) / 128);   // (4, 512)
    xin_gemm<<<gx, 256>>>(x, W_in, b_in, b_lat);

    cudaFuncSetAttribute(rnn_scan, cudaFuncAttributeMaxDynamicSharedMemorySize,
                         SMEM_SCAN_FLOATS * (int)sizeof(float));
    rnn_scan<<<B_DIM, 256, SMEM_SCAN_FLOATS * sizeof(float)>>>(h, W_lat, out);
}